// round 17
// baseline (speedup 1.0000x reference)
#include <cuda_runtime.h>
#include <cuda_bf16.h>
#include <cstdint>

#define N_NODES   50000
#define N_EDGES   1600000
#define F_IN      128
#define F_OUT     8
#define K_TAPS    4
#define MAX_POWER 25            // F_OUT*(K_TAPS-1)+1

#define CHUNKS      2
#define CHUNK_N     (N_NODES / CHUNKS)      // 25000 nodes per column chunk
#define CHUNK_BYTES (CHUNK_N * 4)           // 100000 B
#define NKEYS       (N_NODES * CHUNKS)      // 100000 keys: key = chunk*N + row
#define KPC         ((NKEYS + 147) / 148)   // 676 keys per CTA

#define GRID_P    148           // persistent grid: 1 CTA/SM, all co-resident
#define T_P       1024
#define ROWS_PER_CTA ((N_NODES + GRID_P - 1) / GRID_P)   // 338
#define SMEM_BYTES (N_NODES * 4)                          // 200 KB dynamic

// ---- device-global scratch ----
__device__ __align__(16) float g_s[(MAX_POWER + 1) * N_NODES];  // 5.2 MB
__device__ int      g_cnt[NKEYS];
__device__ int      g_rowptr[NKEYS + 1];
__device__ int      g_fill[NKEYS];
__device__ int2     g_csr[N_EDGES];        // {(row<<16)|col, val-bits}
__device__ int      g_part[GRID_P];
__device__ unsigned g_arrive;
__device__ unsigned g_epoch;
__device__ unsigned g_done;

// ---------------------------------------------------------------------------
// mbarrier + TMA bulk-copy helpers
// ---------------------------------------------------------------------------
__device__ __forceinline__ unsigned smem_u32(const void* p) {
    return (unsigned)__cvta_generic_to_shared(p);
}
__device__ __forceinline__ void mbar_init(unsigned mbar, unsigned count) {
    asm volatile("mbarrier.init.shared.b64 [%0], %1;" :: "r"(mbar), "r"(count) : "memory");
}
__device__ __forceinline__ void mbar_expect_tx(unsigned mbar, unsigned bytes) {
    asm volatile("mbarrier.arrive.expect_tx.shared.b64 _, [%0], %1;"
                 :: "r"(mbar), "r"(bytes) : "memory");
}
__device__ __forceinline__ void tma_bulk_g2s(unsigned dst_smem, const void* src,
                                             unsigned bytes, unsigned mbar) {
    asm volatile("cp.async.bulk.shared::cta.global.mbarrier::complete_tx::bytes "
                 "[%0], [%1], %2, [%3];"
                 :: "r"(dst_smem), "l"(src), "r"(bytes), "r"(mbar) : "memory");
}
__device__ __forceinline__ void mbar_wait(unsigned mbar, unsigned parity) {
    asm volatile(
        "{\n\t"
        ".reg .pred P;\n\t"
        "WAIT_%=:\n\t"
        "mbarrier.try_wait.parity.acquire.cta.shared::cta.b64 P, [%0], %1, 0x989680;\n\t"
        "@P bra.uni DONE_%=;\n\t"
        "bra.uni WAIT_%=;\n\t"
        "DONE_%=:\n\t"
        "}"
        :: "r"(mbar), "r"(parity) : "memory");
}

// ---------------------------------------------------------------------------
// Device-wide barrier: one atomic arrive per CTA; last arriver publishes.
// ---------------------------------------------------------------------------
__device__ __forceinline__ void grid_barrier(unsigned target) {
    __syncthreads();
    if (threadIdx.x == 0) {
        __threadfence();
        unsigned arrived = atomicAdd(&g_arrive, 1u) + 1u;
        if (arrived == target * GRID_P) {
            __threadfence();
            *(volatile unsigned*)&g_epoch = target;
        } else {
            while (*(volatile unsigned*)&g_epoch < target) __nanosleep(32);
        }
        __threadfence();
    }
    __syncthreads();
}

// ---------------------------------------------------------------------------
// ONE fused persistent kernel.
// Phase E uses edge-parallel segmented-scan SpMV: coalesced edge loads, no
// rowptr in the inner loop, RED.ADD for segment tails.
// ---------------------------------------------------------------------------
__global__ void __launch_bounds__(T_P, 1)
gfl_fused_kernel(const float* __restrict__ x,
                 const int*   __restrict__ rows,
                 const int*   __restrict__ cols,
                 const float* __restrict__ vals,
                 const float* __restrict__ coeff,
                 float*       __restrict__ y) {
    extern __shared__ float sv[];                 // N_NODES floats (dynamic)
    __shared__ int scanbuf[T_P];
    __shared__ int s_base;
    __shared__ __align__(8) unsigned long long s_mbar[2];

    const int tid  = threadIdx.x;
    const int wid  = tid >> 5;
    const int lane = tid & 31;
    const int cta  = blockIdx.x;

    const int r0 = cta * ROWS_PER_CTA;
    int r1 = r0 + ROWS_PER_CTA; if (r1 > N_NODES) r1 = N_NODES;

    const int kbase = cta * KPC;
    int kend = kbase + KPC; if (kend > NKEYS) kend = NKEYS;
    const int nk = kend - kbase;                  // <= 676
    unsigned bar = 0;

    const unsigned sv_u32 = smem_u32(sv);
    const unsigned mb0 = smem_u32(&s_mbar[0]);
    const unsigned mb1 = smem_u32(&s_mbar[1]);
    if (tid == 0) { mbar_init(mb0, 1); mbar_init(mb1, 1); }

    // ---- phase A: zero key counters + zero g_s[1] slice + rowsum v0 ----
    for (int i = kbase + tid; i < kend; i += T_P) g_cnt[i] = 0;
    for (int n = r0 + tid; n < r1; n += T_P) g_s[N_NODES + n] = 0.0f;
    for (int n = r0 + wid; n < r1; n += 32) {
        const float4* xr = reinterpret_cast<const float4*>(x + (size_t)n * F_IN);
        float4 v = __ldg(&xr[lane]);
        float s = v.x + v.y + v.z + v.w;
        #pragma unroll
        for (int o = 16; o; o >>= 1) s += __shfl_xor_sync(0xffffffffu, s, o);
        if (lane == 0) g_s[n] = s;
    }
    grid_barrier(++bar);

    // ---- phase B: histogram over chunk-major keys, int4-vectorized ----
    {
        const int4* rows4 = reinterpret_cast<const int4*>(rows);
        const int4* cols4 = reinterpret_cast<const int4*>(cols);
        const int total4 = N_EDGES / 4;
        for (int i = cta * T_P + tid; i < total4; i += GRID_P * T_P) {
            int4 r = __ldg(&rows4[i]);
            int4 c = __ldg(&cols4[i]);
            atomicAdd(&g_cnt[(c.x >= CHUNK_N ? N_NODES : 0) + r.x], 1);
            atomicAdd(&g_cnt[(c.y >= CHUNK_N ? N_NODES : 0) + r.y], 1);
            atomicAdd(&g_cnt[(c.z >= CHUNK_N ? N_NODES : 0) + r.z], 1);
            atomicAdd(&g_cnt[(c.w >= CHUNK_N ? N_NODES : 0) + r.w], 1);
        }
    }
    grid_barrier(++bar);

    // ---- phase C1: block-local scan of this CTA's key counts ----
    scanbuf[tid] = (tid < nk) ? g_cnt[kbase + tid] : 0;
    __syncthreads();
    #pragma unroll
    for (int off = 1; off < T_P; off <<= 1) {
        int v = (tid >= off) ? scanbuf[tid - off] : 0;
        __syncthreads();
        scanbuf[tid] += v;
        __syncthreads();
    }
    if (tid == 0) g_part[cta] = scanbuf[T_P - 1];
    grid_barrier(++bar);

    // ---- phase C2: prefix of partials -> rowptr + fill cursors ----
    if (tid == 0) {
        int b = 0;
        #pragma unroll 4
        for (int i = 0; i < cta; i++) b += g_part[i];
        s_base = b;
        if (cta == 0) g_rowptr[NKEYS] = N_EDGES;
    }
    __syncthreads();
    if (tid < nk) {
        int pre = s_base + (tid ? scanbuf[tid - 1] : 0);
        g_rowptr[kbase + tid] = pre;
        g_fill  [kbase + tid] = pre;
    }
    grid_barrier(++bar);

    // chunk split point (rowptr complete now)
    const int csplit = __ldg(&g_rowptr[N_NODES]);   // first chunk-1 edge

    // ---- phase D: scatter edges; entry packs (row<<16)|col + val bits ----
    {
        const int4*   rows4 = reinterpret_cast<const int4*>(rows);
        const int4*   cols4 = reinterpret_cast<const int4*>(cols);
        const float4* vals4 = reinterpret_cast<const float4*>(vals);
        const int total4 = N_EDGES / 4;
        for (int i = cta * T_P + tid; i < total4; i += GRID_P * T_P) {
            int4   r = __ldg(&rows4[i]);
            int4   c = __ldg(&cols4[i]);
            float4 v = __ldg(&vals4[i]);
            int p0 = atomicAdd(&g_fill[(c.x >= CHUNK_N ? N_NODES : 0) + r.x], 1);
            int p1 = atomicAdd(&g_fill[(c.y >= CHUNK_N ? N_NODES : 0) + r.y], 1);
            int p2 = atomicAdd(&g_fill[(c.z >= CHUNK_N ? N_NODES : 0) + r.z], 1);
            int p3 = atomicAdd(&g_fill[(c.w >= CHUNK_N ? N_NODES : 0) + r.w], 1);
            g_csr[p0] = make_int2((int)(((unsigned)r.x << 16) | (unsigned)c.x), __float_as_int(v.x));
            g_csr[p1] = make_int2((int)(((unsigned)r.y << 16) | (unsigned)c.y), __float_as_int(v.y));
            g_csr[p2] = make_int2((int)(((unsigned)r.z << 16) | (unsigned)c.z), __float_as_int(v.z));
            g_csr[p3] = make_int2((int)(((unsigned)r.w << 16) | (unsigned)c.w), __float_as_int(v.w));
        }
    }
    grid_barrier(++bar);

    // ---- phase E: 25 power iterations, edge-parallel segmented-scan SpMV ----
    // Per-CTA contiguous edge blocks within each chunk.
    const int per0 = (csplit + GRID_P - 1) / GRID_P;
    int b0 = cta * per0;       if (b0 > csplit) b0 = csplit;
    int e0 = b0 + per0;        if (e0 > csplit) e0 = csplit;
    const int cnt1 = N_EDGES - csplit;
    const int per1 = (cnt1 + GRID_P - 1) / GRID_P;
    int b1 = csplit + cta * per1; if (b1 > N_EDGES) b1 = N_EDGES;
    int e1 = b1 + per1;           if (e1 > N_EDGES) e1 = N_EDGES;
    const int K0 = (e0 - b0 + T_P - 1) / T_P;
    const int K1 = (e1 - b1 + T_P - 1) / T_P;

    for (int p = 1; p <= MAX_POWER; p++) {
        const float* vin  = g_s + (size_t)(p - 1) * N_NODES;
        float* __restrict__ vout = g_s + (size_t)p * N_NODES;
        const unsigned ph = (unsigned)((p - 1) & 1);

        if (tid == 0) {
            mbar_expect_tx(mb0, CHUNK_BYTES);
            tma_bulk_g2s(sv_u32, vin, CHUNK_BYTES, mb0);
            mbar_expect_tx(mb1, CHUNK_BYTES);
            tma_bulk_g2s(sv_u32 + CHUNK_BYTES, vin + CHUNK_N, CHUNK_BYTES, mb1);
        }

        // zero the NEXT output buffer while the TMA fill is in flight
        if (p < MAX_POWER) {
            float* vz = g_s + (size_t)(p + 1) * N_NODES;
            for (int n = r0 + tid; n < r1; n += T_P) vz[n] = 0.0f;
        }

        // --- process one chunk: coalesced edges + segmented scan + RED.ADD ---
        #define GFL_EDGE_CHUNK(MB, PH, BB, EE, KK)                               \
        {                                                                        \
            mbar_wait((MB), (PH));                                               \
            for (int k = 0; k < (KK); k++) {                                     \
                int i = (BB) + k * T_P + tid;                                    \
                bool valid = i < (EE);                                           \
                unsigned rowid = 0xFFFFFFFFu;                                    \
                float prod = 0.0f;                                               \
                if (valid) {                                                     \
                    int2 e = __ldg(&g_csr[i]);                                   \
                    unsigned ex = (unsigned)e.x;                                 \
                    rowid = ex >> 16;                                            \
                    prod  = __int_as_float(e.y) * sv[ex & 0xFFFFu];              \
                }                                                                \
                unsigned prv = __shfl_up_sync(0xffffffffu, rowid, 1);            \
                bool head = (lane == 0) || (prv != rowid);                       \
                unsigned hb = __ballot_sync(0xffffffffu, head);                  \
                unsigned lemask = (2u << lane) - 1u;                             \
                int dist = lane - (31 - __clz(hb & lemask));                     \
                float s = prod;                                                  \
                _Pragma("unroll")                                                \
                for (int d = 1; d < 32; d <<= 1) {                               \
                    float v = __shfl_up_sync(0xffffffffu, s, d);                 \
                    if (d <= dist) s += v;                                       \
                }                                                                \
                unsigned nxt = __shfl_down_sync(0xffffffffu, rowid, 1);          \
                bool tail = (lane == 31) || (nxt != rowid);                      \
                if (valid && tail) atomicAdd(&vout[rowid], s);                   \
            }                                                                    \
        }
        GFL_EDGE_CHUNK(mb0, ph, b0, e0, K0)
        GFL_EDGE_CHUNK(mb1, ph, b1, e1, K1)
        #undef GFL_EDGE_CHUNK

        grid_barrier(++bar);
    }

    // ---- phase F: y[n,o] = sum_k coeff[o,k] * s[1 + o*(K-1) + k][n] ----
    for (int n = r0 + tid; n < r1; n += T_P) {
        float svv[MAX_POWER];
        #pragma unroll
        for (int p = 0; p < MAX_POWER; p++)
            svv[p] = g_s[(size_t)(p + 1) * N_NODES + n];
        #pragma unroll
        for (int o = 0; o < F_OUT; o++) {
            float acc = 0.0f;
            #pragma unroll
            for (int k = 0; k < K_TAPS; k++)
                acc += __ldg(&coeff[o * K_TAPS + k]) * svv[o * (K_TAPS - 1) + k];
            y[(size_t)n * F_OUT + o] = acc;
        }
    }

    // ---- reset barrier state for next launch/replay (last finisher) ----
    __syncthreads();
    if (tid == 0) {
        __threadfence();
        unsigned old = atomicAdd(&g_done, 1u);
        if (old == GRID_P - 1) {
            g_arrive = 0u;
            g_epoch  = 0u;
            g_done   = 0u;
            __threadfence();
        }
    }
}

// ---------------------------------------------------------------------------
extern "C" void kernel_launch(void* const* d_in, const int* in_sizes, int n_in,
                              void* d_out, int out_size) {
    const float* x     = (const float*)d_in[0];
    const int*   rows  = (const int*)  d_in[1];
    const int*   cols  = (const int*)  d_in[2];
    const float* vals  = (const float*)d_in[3];
    const float* coeff = (const float*)d_in[4];
    float*       y     = (float*)d_out;

    cudaFuncSetAttribute(gfl_fused_kernel,
                         cudaFuncAttributeMaxDynamicSharedMemorySize, SMEM_BYTES);

    gfl_fused_kernel<<<GRID_P, T_P, SMEM_BYTES>>>(x, rows, cols, vals, coeff, y);
}